// round 15
// baseline (speedup 1.0000x reference)
#include <cuda_runtime.h>
#include <cuda_fp16.h>
#include <cstdint>
#include <cstddef>

// ---------------- problem constants ----------------
#define NE   100000      // entities
#define NRL  16          // relations
#define DIM  64
#define EE   1600000     // edges
#define PROJ_TILES 782   // ceil(NE/128)
#define SCAN_B 196       // ceil(NE/512)
#define SORT_CHUNK 2048
#define SORT_B 782       // ceil(EE/2048)

// ---------------- device scratch (static: no runtime alloc allowed) -------
__device__ __align__(128) __half g_proj[(size_t)NRL * NE * DIM]; // 204.8 MB fp16
__device__ __align__(128) __half g_enth[NE * DIM];               // ent as fp16
__device__ __align__(128) __half g_Wh[NRL * DIM * DIM];          // W_R^T fp16: [r][e][d]
__device__ int2  g_es[EE];          // relation-sorted: {src | etype<<20, dst}
__device__ float g_expv[EE];
__device__ float g_denom[NE];
__device__ int   g_deg[NE];
__device__ int   g_off[NE];
__device__ int   g_cur[NE];
__device__ int   g_part[SCAN_B];
__device__ int   g_bcnt[SORT_B * NRL];   // per-chunk relation counts
__device__ int   g_boff[SORT_B * NRL];   // per-chunk exclusive offsets (global)
__device__ int2  g_csr[EE];         // {src, bits(w)}
__device__ __align__(128) float  g_h1[NE * DIM];  // un-normalized layer-0 out (fp32)
__device__ __align__(128) __half g_h1h[NE * DIM]; // same, fp16 gather table
__device__ int   g_is64;

__device__ __forceinline__ float tanhap(float x) {
    float y; asm("tanh.approx.f32 %0, %1;" : "=f"(y) : "f"(x)); return y;
}

// ================= K0: init = dtype detect + per-chunk hist + conversions =
// grid = SORT_B blocks x 256. Block b histograms edge chunk b; grid-stride
// loops cover zeroing + fp16 conversions + out[:, :64] copy.
__global__ void __launch_bounds__(256) k_init(const float* __restrict__ ent,
                                              const float* __restrict__ WR,
                                              const void* __restrict__ srcp,
                                              const void* __restrict__ etp,
                                              float* __restrict__ out) {
    __shared__ int cnt[NRL];
    __shared__ int sIs64;
    int tid = threadIdx.x;
    if (tid < NRL) cnt[tid] = 0;
    if (tid == 0) {
        const long long* p = (const long long*)srcp;
        int ok = 1;
        for (int i = 0; i < 32; i++) {
            long long v = p[i];
            if (v < 0 || v >= NE) ok = 0;
        }
        sIs64 = ok;
        if (blockIdx.x == 0) g_is64 = ok;
    }
    __syncthreads();
    int is64 = sIs64;

    // per-chunk relation histogram
    int base = blockIdx.x * SORT_CHUNK;
    if (is64) {
        const long long* e = (const long long*)etp;
        for (int i = base + tid; i < base + SORT_CHUNK && i < EE; i += 256)
            atomicAdd(&cnt[(int)e[i]], 1);
    } else {
        const int* e = (const int*)etp;
        for (int i = base + tid; i < base + SORT_CHUNK && i < EE; i += 256)
            atomicAdd(&cnt[e[i]], 1);
    }
    __syncthreads();
    if (tid < NRL) g_bcnt[blockIdx.x * NRL + tid] = cnt[tid];

    // grid-stride work
    int gt = blockIdx.x * 256 + tid;
    int stp = SORT_B * 256;
    for (int i = gt; i < NE; i += stp) { g_denom[i] = 0.f; g_deg[i] = 0; }
    for (int i = gt; i < NE * DIM; i += stp) {
        float v = ent[i];
        g_enth[i] = __float2half(v);
        out[(size_t)(i >> 6) * 160 + (i & 63)] = v;
    }
    // W_R transposed to [r][e][d] fp16
    for (int i = gt; i < NRL * DIM * DIM; i += stp) {
        int r = i >> 12, rem = i & 4095, e = rem >> 6, d = rem & 63;
        g_Wh[i] = __float2half(WR[(r << 12) + (d << 6) + e]);
    }
}

// ================= K0c: full exclusive prefix over (chunk, relation) ======
// boff[b][r] = rbase[r] + sum_{b'<b} bcnt[b'][r]; single block.
__global__ void k_roff() {
    __shared__ int tot[NRL];
    __shared__ int basev[NRL];
    int tid = threadIdx.x;
    if (tid < NRL) {
        int run = 0;
        for (int b = 0; b < SORT_B; b++) {
            int t = g_bcnt[b * NRL + tid];
            g_boff[b * NRL + tid] = run;     // relation-local prefix
            run += t;
        }
        tot[tid] = run;
    }
    __syncthreads();
    if (tid == 0) {
        int run = 0;
        for (int r = 0; r < NRL; r++) { int t = tot[r]; basev[r] = run; run += t; }
    }
    __syncthreads();
    if (tid < NRL) {
        int bs = basev[tid];
        for (int b = 0; b < SORT_B; b++) g_boff[b * NRL + tid] += bs;
    }
}

// ================= K0d: single-pass scatter into relation-sorted array ====
__global__ void __launch_bounds__(256) k_sort(const void* __restrict__ srcp,
                                              const void* __restrict__ dstp,
                                              const void* __restrict__ etp) {
    __shared__ int cur[NRL];
    int tid = threadIdx.x;
    if (tid < NRL) cur[tid] = g_boff[blockIdx.x * NRL + tid];
    __syncthreads();
    int base = blockIdx.x * SORT_CHUNK;
    int is64 = g_is64;
    for (int i = base + tid; i < base + SORT_CHUNK && i < EE; i += 256) {
        int s, d, r;
        if (is64) {
            s = (int)((const long long*)srcp)[i];
            d = (int)((const long long*)dstp)[i];
            r = (int)((const long long*)etp)[i];
        } else {
            s = ((const int*)srcp)[i];
            d = ((const int*)dstp)[i];
            r = ((const int*)etp)[i];
        }
        int p = atomicAdd(&cur[r], 1);
        g_es[p] = make_int2(s | (r << 20), d);
        atomicAdd(&g_deg[d], 1);
    }
}

// ================= K2: proj GEMM via mma.sync (f16 in, f32 acc) ===========
// proj[r,n,e] = sum_d ent[n,d] * W_R[r,d,e].  Block: 128 nodes, all 16 rel.
#define STRA 72
__global__ void __launch_bounds__(256) k_proj() {
    __shared__ __half sA[128 * STRA];   // ent tile  [row][k(d)]
    __shared__ __half sB[64 * STRA];    // Wt tile   [n(e)][k(d)]
    __shared__ __half sO[128 * STRA];   // output staging
    int tid = threadIdx.x;
    int wid = tid >> 5, lane = tid & 31;
    int g = lane >> 2, tg = lane & 3;
    int row0 = blockIdx.x * 128;
    int m0 = wid * 16;

    // stage A once (uint4 from fp16 table)
    {
        const uint4 zero4 = make_uint4(0, 0, 0, 0);
        const uint4* Ap = (const uint4*)g_enth;
        for (int c = tid; c < 1024; c += 256) {
            int row = c >> 3, q = c & 7;
            int node = row0 + row;
            uint4 v = (node < NE) ? Ap[(size_t)node * 8 + q] : zero4;
            *(uint4*)&sA[row * STRA + q * 8] = v;
        }
    }

    for (int r = 0; r < NRL; r++) {
        __syncthreads();
        {   // stage B (already transposed+fp16): sB[e][d]
            const uint4* Bp = (const uint4*)(g_Wh + (r << 12));
            for (int c = tid; c < 512; c += 256) {
                int e = c >> 3, q = c & 7;
                *(uint4*)&sB[e * STRA + q * 8] = Bp[c];
            }
        }
        __syncthreads();

        float acc[8][4];
#pragma unroll
        for (int nt = 0; nt < 8; nt++)
#pragma unroll
            for (int j = 0; j < 4; j++) acc[nt][j] = 0.f;

#pragma unroll
        for (int kt = 0; kt < 4; kt++) {
            int k0 = kt * 16;
            const __half* pa = &sA[(m0 + g) * STRA + k0 + 2 * tg];
            uint32_t a0 = *(const uint32_t*)pa;
            uint32_t a1 = *(const uint32_t*)(pa + 8 * STRA);
            uint32_t a2 = *(const uint32_t*)(pa + 8);
            uint32_t a3 = *(const uint32_t*)(pa + 8 * STRA + 8);
#pragma unroll
            for (int nt = 0; nt < 8; nt++) {
                const __half* pb = &sB[(nt * 8 + g) * STRA + k0 + 2 * tg];
                uint32_t b0 = *(const uint32_t*)pb;
                uint32_t b1 = *(const uint32_t*)(pb + 8);
                asm volatile(
                    "mma.sync.aligned.m16n8k16.row.col.f32.f16.f16.f32 "
                    "{%0,%1,%2,%3},{%4,%5,%6,%7},{%8,%9},{%0,%1,%2,%3};\n"
                    : "+f"(acc[nt][0]), "+f"(acc[nt][1]),
                      "+f"(acc[nt][2]), "+f"(acc[nt][3])
                    : "r"(a0), "r"(a1), "r"(a2), "r"(a3), "r"(b0), "r"(b1));
            }
        }
        // fragment -> smem staging (padded, conflict-free)
        {
            int rowA = m0 + g, rowB = rowA + 8;
#pragma unroll
            for (int nt = 0; nt < 8; nt++) {
                *(__half2*)&sO[rowA * STRA + nt * 8 + tg * 2] =
                    __floats2half2_rn(acc[nt][0], acc[nt][1]);
                *(__half2*)&sO[rowB * STRA + nt * 8 + tg * 2] =
                    __floats2half2_rn(acc[nt][2], acc[nt][3]);
            }
        }
        __syncthreads();
        // coalesced 128B-chunk store to g_proj
        for (int c = tid; c < 1024; c += 256) {
            int row = c >> 3, q = c & 7;
            int node = row0 + row;
            if (node < NE)
                ((uint4*)(g_proj + ((size_t)r * NE + node) * 64))[q] =
                    *(const uint4*)&sO[row * STRA + q * 8];
        }
    }
}

// ================= K3: attention over relation-sorted edges ===============
// 8 lanes per edge, 2 edges per 8-lane group (MLP=4). 64 edges / 256-thr block.
// Sorted order => both gathers land in one 12.8MB L2-resident relation slab.
__global__ void __launch_bounds__(256) k_att(const float* __restrict__ rel) {
    __shared__ float sRel[NRL * DIM];
    int tid = threadIdx.x;
    for (int i = tid; i < NRL * DIM; i += 256) sRel[i] = rel[i];
    __syncthreads();

    int g8 = tid >> 3, lane8 = tid & 7;
    int e0 = blockIdx.x * 64 + g8;
    int e1 = e0 + 32;
    int2 ei0 = g_es[e0];
    int2 ei1 = g_es[e1];
    int s0 = ei0.x & 0xFFFFF, r0 = ei0.x >> 20, d0 = ei0.y;
    int s1 = ei1.x & 0xFFFFF, r1 = ei1.x >> 20, d1 = ei1.y;

    const uint4* P = (const uint4*)g_proj;          // 16B chunks, u32 index ok
    uint32_t it0 = (uint32_t)(r0 * NE + s0) * 8u + (uint32_t)lane8;
    uint32_t ih0 = (uint32_t)(r0 * NE + d0) * 8u + (uint32_t)lane8;
    uint32_t it1 = (uint32_t)(r1 * NE + s1) * 8u + (uint32_t)lane8;
    uint32_t ih1 = (uint32_t)(r1 * NE + d1) * 8u + (uint32_t)lane8;
    uint4 t40 = P[it0];                             // 4 independent loads
    uint4 h40 = P[ih0];
    uint4 t41 = P[it1];
    uint4 h41 = P[ih1];

    const float* rl0 = &sRel[r0 * 64 + lane8 * 8];
    const float* rl1 = &sRel[r1 * 64 + lane8 * 8];
    const __half2* tw0 = (const __half2*)&t40;
    const __half2* hw0 = (const __half2*)&h40;
    const __half2* tw1 = (const __half2*)&t41;
    const __half2* hw1 = (const __half2*)&h41;

    float att0 = 0.f, att1 = 0.f;
#pragma unroll
    for (int j = 0; j < 4; j++) {
        float2 tf = __half22float2(tw0[j]);
        float2 hf = __half22float2(hw0[j]);
        att0 = fmaf(tf.x, tanhap(hf.x + rl0[2 * j]),     att0);
        att0 = fmaf(tf.y, tanhap(hf.y + rl0[2 * j + 1]), att0);
        float2 tg = __half22float2(tw1[j]);
        float2 hg = __half22float2(hw1[j]);
        att1 = fmaf(tg.x, tanhap(hg.x + rl1[2 * j]),     att1);
        att1 = fmaf(tg.y, tanhap(hg.y + rl1[2 * j + 1]), att1);
    }
#pragma unroll
    for (int o = 4; o; o >>= 1) {
        att0 += __shfl_xor_sync(0xFFFFFFFF, att0, o);
        att1 += __shfl_xor_sync(0xFFFFFFFF, att1, o);
    }
    if (lane8 == 0) {
        float ev0 = __expf(att0);   // |att| small: no max-shift needed
        float ev1 = __expf(att1);
        g_expv[e0] = ev0;
        g_expv[e1] = ev1;
        atomicAdd(&g_denom[d0], ev0);
        atomicAdd(&g_denom[d1], ev1);
    }
}

// ================= K4-6: exclusive scan of degrees ========================
__global__ void k_scan1() {
    __shared__ int sm[512];
    int tid = threadIdx.x;
    int i = blockIdx.x * 512 + tid;
    int x = (i < NE) ? g_deg[i] : 0;
    sm[tid] = x;
    for (int o = 1; o < 512; o <<= 1) {
        __syncthreads();
        int t = (tid >= o) ? sm[tid - o] : 0;
        __syncthreads();
        sm[tid] += t;
    }
    __syncthreads();
    if (i < NE) g_off[i] = sm[tid] - x;        // block-local exclusive
    if (tid == 511) g_part[blockIdx.x] = sm[511];
}
__global__ void k_scan2() {
    if (threadIdx.x == 0) {
        int run = 0;
        for (int b = 0; b < SCAN_B; b++) {
            int t = g_part[b]; g_part[b] = run; run += t;
        }
    }
}
__global__ void k_scan3() {
    int i = blockIdx.x * 512 + threadIdx.x;
    if (i < NE) {
        int o = g_off[i] + g_part[blockIdx.x];
        g_off[i] = o;
        g_cur[i] = o;
    }
}

// ================= K7: scatter edges into dst-CSR with softmax weight =====
__global__ void __launch_bounds__(256) k_scatter() {
    int e = blockIdx.x * 256 + threadIdx.x;
    int2 ei = g_es[e];
    int d = ei.y;
    int p = atomicAdd(&g_cur[d], 1);
    float w = g_expv[e] / g_denom[d];
    g_csr[p] = make_int2(ei.x & 0xFFFFF, __float_as_int(w));
}

// ================= K8: fused KGAT layer, fp16 neighbor gathers ============
// One warp per node. Gathers from fp16 table tblh (128B/edge), own h + GEMV fp32.
template <int OUT>
__global__ void __launch_bounds__(256) k_layer(const float* __restrict__ hin,
                                               const __half* __restrict__ tblh,
                                               const float* __restrict__ W,
                                               float* __restrict__ hraw,
                                               __half* __restrict__ hout16,
                                               float* __restrict__ out,
                                               int col0) {
    __shared__ float sW[64 * OUT];
    __shared__ float sv[8][64];
    __shared__ int   sS[8][33];
    __shared__ float sF[8][33];
    int tid = threadIdx.x;
    for (int i = tid; i < 64 * OUT; i += 256) sW[i] = W[i];
    __syncthreads();

    int wid = tid >> 5, lane = tid & 31;
    int n = blockIdx.x * 8 + wid;          // grid exactly 12500 -> n < NE

    // own h, dims (2*lane, 2*lane+1), fp32
    float2 hown = *(const float2*)(hin + (size_t)n * 64 + 2 * lane);
    int beg = g_off[n];
    int cnt = g_deg[n];

    float ax = 0.f, ay = 0.f;                  // agg dims 2*lane, 2*lane+1
    for (int base = 0; base < cnt; base += 32) {
        int m = cnt - base; if (m > 32) m = 32;
        if (lane < m) {
            int2 ew = g_csr[beg + base + lane];
            sS[wid][lane] = ew.x;
            sF[wid][lane] = __int_as_float(ew.y);
        }
        __syncwarp();
        int j = 0;
        for (; j + 4 <= m; j += 4) {           // 4 independent 4B gathers / iter
            int s0 = sS[wid][j], s1 = sS[wid][j + 1];
            int s2 = sS[wid][j + 2], s3 = sS[wid][j + 3];
            float w0 = sF[wid][j], w1 = sF[wid][j + 1];
            float w2 = sF[wid][j + 2], w3 = sF[wid][j + 3];
            float2 v0 = __half22float2(((const __half2*)(tblh + ((size_t)s0 << 6)))[lane]);
            float2 v1 = __half22float2(((const __half2*)(tblh + ((size_t)s1 << 6)))[lane]);
            float2 v2 = __half22float2(((const __half2*)(tblh + ((size_t)s2 << 6)))[lane]);
            float2 v3 = __half22float2(((const __half2*)(tblh + ((size_t)s3 << 6)))[lane]);
            ax = fmaf(w0, v0.x, ax); ay = fmaf(w0, v0.y, ay);
            ax = fmaf(w1, v1.x, ax); ay = fmaf(w1, v1.y, ay);
            ax = fmaf(w2, v2.x, ax); ay = fmaf(w2, v2.y, ay);
            ax = fmaf(w3, v3.x, ax); ay = fmaf(w3, v3.y, ay);
        }
        for (; j < m; j++) {
            int s = sS[wid][j];
            float w = sF[wid][j];
            float2 v = __half22float2(((const __half2*)(tblh + ((size_t)s << 6)))[lane]);
            ax = fmaf(w, v.x, ax); ay = fmaf(w, v.y, ay);
        }
        __syncwarp();
    }
    sv[wid][2 * lane]     = hown.x * ax;
    sv[wid][2 * lane + 1] = hown.y * ay;
    __syncwarp();

    if (OUT == 64) {
        float o0 = 0.f, o1 = 0.f;
#pragma unroll 8
        for (int k = 0; k < 64; k++) {
            float vk = sv[wid][k];
            o0 = fmaf(vk, sW[k * 64 + lane], o0);
            o1 = fmaf(vk, sW[k * 64 + lane + 32], o1);
        }
        o0 = (o0 > 0.f) ? o0 : 0.01f * o0;
        o1 = (o1 > 0.f) ? o1 : 0.01f * o1;
        hraw[(size_t)n * 64 + lane]      = o0;
        hraw[(size_t)n * 64 + 32 + lane] = o1;
        // repack to fp16 gather table via smem (dims 2*lane, 2*lane+1)
        __syncwarp();
        sv[wid][lane]      = o0;
        sv[wid][lane + 32] = o1;
        __syncwarp();
        *(__half2*)(hout16 + ((size_t)n << 6) + 2 * lane) =
            __floats2half2_rn(sv[wid][2 * lane], sv[wid][2 * lane + 1]);
        float ss = o0 * o0 + o1 * o1;
#pragma unroll
        for (int o = 16; o; o >>= 1) ss += __shfl_xor_sync(0xFFFFFFFF, ss, o);
        float sc = 1.f / fmaxf(sqrtf(ss), 1e-12f);
        out[(size_t)n * 160 + col0 + lane]      = o0 * sc;
        out[(size_t)n * 160 + col0 + 32 + lane] = o1 * sc;
    } else {
        float o0 = 0.f;
#pragma unroll 8
        for (int k = 0; k < 64; k++)
            o0 = fmaf(sv[wid][k], sW[k * 32 + lane], o0);
        o0 = (o0 > 0.f) ? o0 : 0.01f * o0;
        float ss = o0 * o0;
#pragma unroll
        for (int o = 16; o; o >>= 1) ss += __shfl_xor_sync(0xFFFFFFFF, ss, o);
        float sc = 1.f / fmaxf(sqrtf(ss), 1e-12f);
        out[(size_t)n * 160 + col0 + lane] = o0 * sc;
    }
}

// ================= launch =================================================
extern "C" void kernel_launch(void* const* d_in, const int* in_sizes, int n_in,
                              void* d_out, int out_size) {
    const float* ent = (const float*)d_in[0];   // [NE, 64]
    const float* rel = (const float*)d_in[1];   // [16, 64]
    const float* WR  = (const float*)d_in[2];   // [16, 64, 64]
    const float* W0  = (const float*)d_in[3];   // [64, 64]
    const float* W1  = (const float*)d_in[4];   // [64, 32]
    const void*  src = d_in[5];
    const void*  dst = d_in[6];
    const void*  et  = d_in[7];
    float* out = (float*)d_out;                 // [NE, 160]

    float* h1raw;   cudaGetSymbolAddress((void**)&h1raw, g_h1);
    __half* h1h;    cudaGetSymbolAddress((void**)&h1h,  g_h1h);
    __half* enth;   cudaGetSymbolAddress((void**)&enth, g_enth);

    k_init<<<SORT_B, 256>>>(ent, WR, src, et, out);      // 0
    k_roff<<<1, 256>>>();                                // 1
    k_sort<<<SORT_B, 256>>>(src, dst, et);               // 2
    k_proj<<<PROJ_TILES, 256>>>();                       // 3  <- ncu slot
    k_att<<<EE / 64, 256>>>(rel);                        // 4
    k_scan1<<<SCAN_B, 512>>>();                          // 5
    k_scan2<<<1, 32>>>();                                // 6
    k_scan3<<<SCAN_B, 512>>>();                          // 7
    k_scatter<<<EE / 256, 256>>>();                      // 8
    k_layer<64><<<NE / 8, 256>>>(ent,   enth, W0, h1raw, h1h, out, 64);
    k_layer<32><<<NE / 8, 256>>>(h1raw, h1h,  W1, h1raw, h1h, out, 128);
}

// round 17
// speedup vs baseline: 1.2219x; 1.2219x over previous
#include <cuda_runtime.h>
#include <cuda_fp16.h>
#include <cstdint>
#include <cstddef>

// ---------------- problem constants ----------------
#define NE   100000      // entities
#define NRL  16          // relations
#define DIM  64
#define EE   1600000     // edges
#define PROJ_TILES 782   // ceil(NE/128)
#define PROJ_GRID  592   // 4 CTA/SM x 148 SMs, persistent
#define SCAN_B 196       // ceil(NE/512)
#define SORT_CHUNK 2048
#define SORT_B 782       // ceil(EE/2048)

// ---------------- device scratch (static: no runtime alloc allowed) -------
__device__ __align__(128) __half g_proj[(size_t)NRL * NE * DIM]; // 204.8 MB fp16
__device__ __align__(128) __half g_enth[NE * DIM];               // ent as fp16
__device__ __align__(128) __half g_Wh[NRL * DIM * DIM];          // W_R^T fp16: [r][e][d]
__device__ int2  g_es[EE];          // relation-sorted: {src | etype<<20, dst}
__device__ float g_expv[EE];
__device__ float g_denom[NE];
__device__ int   g_deg[NE];
__device__ int   g_off[NE];
__device__ int   g_cur[NE];
__device__ int   g_part[SCAN_B];
__device__ int   g_bcnt[SORT_B * NRL];   // per-chunk relation counts
__device__ int   g_boff[SORT_B * NRL];   // per-chunk relation-local prefix
__device__ int   g_rtot[NRL];
__device__ int   g_rbase[NRL];
__device__ int2  g_csr[EE];         // {src, bits(w)}
__device__ __align__(128) float  g_h1[NE * DIM];  // un-normalized layer-0 out (fp32)
__device__ __align__(128) __half g_h1h[NE * DIM]; // same, fp16 gather table
__device__ int   g_is64;

__device__ __forceinline__ float tanhap(float x) {
    float y; asm("tanh.approx.f32 %0, %1;" : "=f"(y) : "f"(x)); return y;
}

// ================= K0: init = dtype detect + per-chunk hist + conversions =
__global__ void __launch_bounds__(256) k_init(const float* __restrict__ ent,
                                              const float* __restrict__ WR,
                                              const void* __restrict__ srcp,
                                              const void* __restrict__ etp,
                                              float* __restrict__ out) {
    __shared__ int cnt[NRL];
    __shared__ int sIs64;
    int tid = threadIdx.x;
    if (tid < NRL) cnt[tid] = 0;
    if (tid == 0) {
        const long long* p = (const long long*)srcp;
        int ok = 1;
        for (int i = 0; i < 32; i++) {
            long long v = p[i];
            if (v < 0 || v >= NE) ok = 0;
        }
        sIs64 = ok;
        if (blockIdx.x == 0) g_is64 = ok;
    }
    __syncthreads();
    int is64 = sIs64;

    // per-chunk relation histogram
    int base = blockIdx.x * SORT_CHUNK;
    if (is64) {
        const long long* e = (const long long*)etp;
        for (int i = base + tid; i < base + SORT_CHUNK && i < EE; i += 256)
            atomicAdd(&cnt[(int)e[i]], 1);
    } else {
        const int* e = (const int*)etp;
        for (int i = base + tid; i < base + SORT_CHUNK && i < EE; i += 256)
            atomicAdd(&cnt[e[i]], 1);
    }
    __syncthreads();
    if (tid < NRL) g_bcnt[blockIdx.x * NRL + tid] = cnt[tid];

    // grid-stride work
    int gt = blockIdx.x * 256 + tid;
    int stp = SORT_B * 256;
    for (int i = gt; i < NE; i += stp) { g_denom[i] = 0.f; g_deg[i] = 0; }
    for (int i = gt; i < NE * DIM; i += stp) {
        float v = ent[i];
        g_enth[i] = __float2half(v);
        out[(size_t)(i >> 6) * 160 + (i & 63)] = v;
    }
    // W_R transposed to [r][e][d] fp16
    for (int i = gt; i < NRL * DIM * DIM; i += stp) {
        int r = i >> 12, rem = i & 4095, e = rem >> 6, d = rem & 63;
        g_Wh[i] = __float2half(WR[(r << 12) + (d << 6) + e]);
    }
}

// ================= K0b: parallel per-relation scan over chunks ============
// Block r scans g_bcnt[:, r] (782 values) -> relation-local exclusive prefix.
__global__ void __launch_bounds__(256) k_roff1() {
    __shared__ int part[256];
    int r = blockIdx.x, tid = threadIdx.x;
    int b0 = tid * 4;
    int v0 = (b0 + 0 < SORT_B) ? g_bcnt[(b0 + 0) * NRL + r] : 0;
    int v1 = (b0 + 1 < SORT_B) ? g_bcnt[(b0 + 1) * NRL + r] : 0;
    int v2 = (b0 + 2 < SORT_B) ? g_bcnt[(b0 + 2) * NRL + r] : 0;
    int v3 = (b0 + 3 < SORT_B) ? g_bcnt[(b0 + 3) * NRL + r] : 0;
    int s = v0 + v1 + v2 + v3;
    part[tid] = s;
    for (int o = 1; o < 256; o <<= 1) {
        __syncthreads();
        int t = (tid >= o) ? part[tid - o] : 0;
        __syncthreads();
        part[tid] += t;
    }
    __syncthreads();
    int run = part[tid] - s;                    // exclusive prefix of group
    if (b0 + 0 < SORT_B) g_boff[(b0 + 0) * NRL + r] = run;
    run += v0;
    if (b0 + 1 < SORT_B) g_boff[(b0 + 1) * NRL + r] = run;
    run += v1;
    if (b0 + 2 < SORT_B) g_boff[(b0 + 2) * NRL + r] = run;
    run += v2;
    if (b0 + 3 < SORT_B) g_boff[(b0 + 3) * NRL + r] = run;
    if (tid == 0) g_rtot[r] = part[255];
}
// 16-way exclusive scan of relation totals.
__global__ void k_roff2() {
    if (threadIdx.x == 0) {
        int run = 0;
        for (int r = 0; r < NRL; r++) { int t = g_rtot[r]; g_rbase[r] = run; run += t; }
    }
}

// ================= K0d: single-pass scatter into relation-sorted array ====
__global__ void __launch_bounds__(256) k_sort(const void* __restrict__ srcp,
                                              const void* __restrict__ dstp,
                                              const void* __restrict__ etp) {
    __shared__ int cur[NRL];
    int tid = threadIdx.x;
    if (tid < NRL) cur[tid] = g_boff[blockIdx.x * NRL + tid] + g_rbase[tid];
    __syncthreads();
    int base = blockIdx.x * SORT_CHUNK;
    int is64 = g_is64;
    for (int i = base + tid; i < base + SORT_CHUNK && i < EE; i += 256) {
        int s, d, r;
        if (is64) {
            s = (int)((const long long*)srcp)[i];
            d = (int)((const long long*)dstp)[i];
            r = (int)((const long long*)etp)[i];
        } else {
            s = ((const int*)srcp)[i];
            d = ((const int*)dstp)[i];
            r = ((const int*)etp)[i];
        }
        int p = atomicAdd(&cur[r], 1);
        g_es[p] = make_int2(s | (r << 20), d);
        atomicAdd(&g_deg[d], 1);
    }
}

// ================= K2: proj GEMM via mma.sync, persistent grid ============
// proj[r,n,e] = sum_d ent[n,d] * W_R[r,d,e].  Tile: 128 nodes, all 16 rel.
#define STRA 72
__global__ void __launch_bounds__(256) k_proj() {
    __shared__ __half sA[128 * STRA];   // ent tile  [row][k(d)]
    __shared__ __half sB[64 * STRA];    // Wt tile   [n(e)][k(d)]
    __shared__ __half sO[128 * STRA];   // output staging
    int tid = threadIdx.x;
    int wid = tid >> 5, lane = tid & 31;
    int g = lane >> 2, tg = lane & 3;
    int m0 = wid * 16;

    for (int tile = blockIdx.x; tile < PROJ_TILES; tile += PROJ_GRID) {
        int row0 = tile * 128;
        __syncthreads();                 // all warps done with previous tile's sA
        // stage A (uint4 from fp16 table)
        {
            const uint4 zero4 = make_uint4(0, 0, 0, 0);
            const uint4* Ap = (const uint4*)g_enth;
            for (int c = tid; c < 1024; c += 256) {
                int row = c >> 3, q = c & 7;
                int node = row0 + row;
                uint4 v = (node < NE) ? Ap[(size_t)node * 8 + q] : zero4;
                *(uint4*)&sA[row * STRA + q * 8] = v;
            }
        }

        for (int r = 0; r < NRL; r++) {
            __syncthreads();
            {   // stage B (already transposed+fp16): sB[e][d]
                const uint4* Bp = (const uint4*)(g_Wh + (r << 12));
                for (int c = tid; c < 512; c += 256) {
                    int e = c >> 3, q = c & 7;
                    *(uint4*)&sB[e * STRA + q * 8] = Bp[c];
                }
            }
            __syncthreads();

            float acc[8][4];
#pragma unroll
            for (int nt = 0; nt < 8; nt++)
#pragma unroll
                for (int j = 0; j < 4; j++) acc[nt][j] = 0.f;

#pragma unroll
            for (int kt = 0; kt < 4; kt++) {
                int k0 = kt * 16;
                const __half* pa = &sA[(m0 + g) * STRA + k0 + 2 * tg];
                uint32_t a0 = *(const uint32_t*)pa;
                uint32_t a1 = *(const uint32_t*)(pa + 8 * STRA);
                uint32_t a2 = *(const uint32_t*)(pa + 8);
                uint32_t a3 = *(const uint32_t*)(pa + 8 * STRA + 8);
#pragma unroll
                for (int nt = 0; nt < 8; nt++) {
                    const __half* pb = &sB[(nt * 8 + g) * STRA + k0 + 2 * tg];
                    uint32_t b0 = *(const uint32_t*)pb;
                    uint32_t b1 = *(const uint32_t*)(pb + 8);
                    asm volatile(
                        "mma.sync.aligned.m16n8k16.row.col.f32.f16.f16.f32 "
                        "{%0,%1,%2,%3},{%4,%5,%6,%7},{%8,%9},{%0,%1,%2,%3};\n"
                        : "+f"(acc[nt][0]), "+f"(acc[nt][1]),
                          "+f"(acc[nt][2]), "+f"(acc[nt][3])
                        : "r"(a0), "r"(a1), "r"(a2), "r"(a3), "r"(b0), "r"(b1));
                }
            }
            // fragment -> smem staging (padded, conflict-free)
            {
                int rowA = m0 + g, rowB = rowA + 8;
#pragma unroll
                for (int nt = 0; nt < 8; nt++) {
                    *(__half2*)&sO[rowA * STRA + nt * 8 + tg * 2] =
                        __floats2half2_rn(acc[nt][0], acc[nt][1]);
                    *(__half2*)&sO[rowB * STRA + nt * 8 + tg * 2] =
                        __floats2half2_rn(acc[nt][2], acc[nt][3]);
                }
            }
            __syncthreads();
            // coalesced 128B-chunk store to g_proj
            for (int c = tid; c < 1024; c += 256) {
                int row = c >> 3, q = c & 7;
                int node = row0 + row;
                if (node < NE)
                    ((uint4*)(g_proj + ((size_t)r * NE + node) * 64))[q] =
                        *(const uint4*)&sO[row * STRA + q * 8];
            }
        }
    }
}

// ================= K3: attention over relation-sorted edges ===============
// 8 lanes per edge, 2 edges per 8-lane group (MLP=4). 64 edges / 256-thr block.
// Sorted order => both gathers land in one 12.8MB L2-resident relation slab.
__global__ void __launch_bounds__(256) k_att(const float* __restrict__ rel) {
    __shared__ float sRel[NRL * DIM];
    int tid = threadIdx.x;
    for (int i = tid; i < NRL * DIM; i += 256) sRel[i] = rel[i];
    __syncthreads();

    int g8 = tid >> 3, lane8 = tid & 7;
    int e0 = blockIdx.x * 64 + g8;
    int e1 = e0 + 32;
    int2 ei0 = g_es[e0];
    int2 ei1 = g_es[e1];
    int s0 = ei0.x & 0xFFFFF, r0 = ei0.x >> 20, d0 = ei0.y;
    int s1 = ei1.x & 0xFFFFF, r1 = ei1.x >> 20, d1 = ei1.y;

    const uint4* P = (const uint4*)g_proj;          // 16B chunks, u32 index ok
    uint32_t it0 = (uint32_t)(r0 * NE + s0) * 8u + (uint32_t)lane8;
    uint32_t ih0 = (uint32_t)(r0 * NE + d0) * 8u + (uint32_t)lane8;
    uint32_t it1 = (uint32_t)(r1 * NE + s1) * 8u + (uint32_t)lane8;
    uint32_t ih1 = (uint32_t)(r1 * NE + d1) * 8u + (uint32_t)lane8;
    uint4 t40 = P[it0];                             // 4 independent loads
    uint4 h40 = P[ih0];
    uint4 t41 = P[it1];
    uint4 h41 = P[ih1];

    const float* rl0 = &sRel[r0 * 64 + lane8 * 8];
    const float* rl1 = &sRel[r1 * 64 + lane8 * 8];
    const __half2* tw0 = (const __half2*)&t40;
    const __half2* hw0 = (const __half2*)&h40;
    const __half2* tw1 = (const __half2*)&t41;
    const __half2* hw1 = (const __half2*)&h41;

    float att0 = 0.f, att1 = 0.f;
#pragma unroll
    for (int j = 0; j < 4; j++) {
        float2 tf = __half22float2(tw0[j]);
        float2 hf = __half22float2(hw0[j]);
        att0 = fmaf(tf.x, tanhap(hf.x + rl0[2 * j]),     att0);
        att0 = fmaf(tf.y, tanhap(hf.y + rl0[2 * j + 1]), att0);
        float2 tg = __half22float2(tw1[j]);
        float2 hg = __half22float2(hw1[j]);
        att1 = fmaf(tg.x, tanhap(hg.x + rl1[2 * j]),     att1);
        att1 = fmaf(tg.y, tanhap(hg.y + rl1[2 * j + 1]), att1);
    }
#pragma unroll
    for (int o = 4; o; o >>= 1) {
        att0 += __shfl_xor_sync(0xFFFFFFFF, att0, o);
        att1 += __shfl_xor_sync(0xFFFFFFFF, att1, o);
    }
    if (lane8 == 0) {
        float ev0 = __expf(att0);   // |att| small: no max-shift needed
        float ev1 = __expf(att1);
        g_expv[e0] = ev0;
        g_expv[e1] = ev1;
        atomicAdd(&g_denom[d0], ev0);
        atomicAdd(&g_denom[d1], ev1);
    }
}

// ================= K4-6: exclusive scan of degrees ========================
__global__ void k_scan1() {
    __shared__ int sm[512];
    int tid = threadIdx.x;
    int i = blockIdx.x * 512 + tid;
    int x = (i < NE) ? g_deg[i] : 0;
    sm[tid] = x;
    for (int o = 1; o < 512; o <<= 1) {
        __syncthreads();
        int t = (tid >= o) ? sm[tid - o] : 0;
        __syncthreads();
        sm[tid] += t;
    }
    __syncthreads();
    if (i < NE) g_off[i] = sm[tid] - x;        // block-local exclusive
    if (tid == 511) g_part[blockIdx.x] = sm[511];
}
__global__ void k_scan2() {
    if (threadIdx.x == 0) {
        int run = 0;
        for (int b = 0; b < SCAN_B; b++) {
            int t = g_part[b]; g_part[b] = run; run += t;
        }
    }
}
__global__ void k_scan3() {
    int i = blockIdx.x * 512 + threadIdx.x;
    if (i < NE) {
        int o = g_off[i] + g_part[blockIdx.x];
        g_off[i] = o;
        g_cur[i] = o;
    }
}

// ================= K7: scatter edges into dst-CSR with softmax weight =====
__global__ void __launch_bounds__(256) k_scatter() {
    int e = blockIdx.x * 256 + threadIdx.x;
    int2 ei = g_es[e];
    int d = ei.y;
    int p = atomicAdd(&g_cur[d], 1);
    float w = g_expv[e] / g_denom[d];
    g_csr[p] = make_int2(ei.x & 0xFFFFF, __float_as_int(w));
}

// ================= K8: fused KGAT layer, fp16 neighbor gathers ============
// One warp per node. Gathers from fp16 table tblh (128B/edge), own h + GEMV fp32.
template <int OUT>
__global__ void __launch_bounds__(256) k_layer(const float* __restrict__ hin,
                                               const __half* __restrict__ tblh,
                                               const float* __restrict__ W,
                                               float* __restrict__ hraw,
                                               __half* __restrict__ hout16,
                                               float* __restrict__ out,
                                               int col0) {
    __shared__ float sW[64 * OUT];
    __shared__ float sv[8][64];
    __shared__ int   sS[8][33];
    __shared__ float sF[8][33];
    int tid = threadIdx.x;
    for (int i = tid; i < 64 * OUT; i += 256) sW[i] = W[i];
    __syncthreads();

    int wid = tid >> 5, lane = tid & 31;
    int n = blockIdx.x * 8 + wid;          // grid exactly 12500 -> n < NE

    // own h, dims (2*lane, 2*lane+1), fp32
    float2 hown = *(const float2*)(hin + (size_t)n * 64 + 2 * lane);
    int beg = g_off[n];
    int cnt = g_deg[n];

    float ax = 0.f, ay = 0.f;                  // agg dims 2*lane, 2*lane+1
    for (int base = 0; base < cnt; base += 32) {
        int m = cnt - base; if (m > 32) m = 32;
        if (lane < m) {
            int2 ew = g_csr[beg + base + lane];
            sS[wid][lane] = ew.x;
            sF[wid][lane] = __int_as_float(ew.y);
        }
        __syncwarp();
        int j = 0;
        for (; j + 4 <= m; j += 4) {           // 4 independent 4B gathers / iter
            int s0 = sS[wid][j], s1 = sS[wid][j + 1];
            int s2 = sS[wid][j + 2], s3 = sS[wid][j + 3];
            float w0 = sF[wid][j], w1 = sF[wid][j + 1];
            float w2 = sF[wid][j + 2], w3 = sF[wid][j + 3];
            float2 v0 = __half22float2(((const __half2*)(tblh + ((size_t)s0 << 6)))[lane]);
            float2 v1 = __half22float2(((const __half2*)(tblh + ((size_t)s1 << 6)))[lane]);
            float2 v2 = __half22float2(((const __half2*)(tblh + ((size_t)s2 << 6)))[lane]);
            float2 v3 = __half22float2(((const __half2*)(tblh + ((size_t)s3 << 6)))[lane]);
            ax = fmaf(w0, v0.x, ax); ay = fmaf(w0, v0.y, ay);
            ax = fmaf(w1, v1.x, ax); ay = fmaf(w1, v1.y, ay);
            ax = fmaf(w2, v2.x, ax); ay = fmaf(w2, v2.y, ay);
            ax = fmaf(w3, v3.x, ax); ay = fmaf(w3, v3.y, ay);
        }
        for (; j < m; j++) {
            int s = sS[wid][j];
            float w = sF[wid][j];
            float2 v = __half22float2(((const __half2*)(tblh + ((size_t)s << 6)))[lane]);
            ax = fmaf(w, v.x, ax); ay = fmaf(w, v.y, ay);
        }
        __syncwarp();
    }
    sv[wid][2 * lane]     = hown.x * ax;
    sv[wid][2 * lane + 1] = hown.y * ay;
    __syncwarp();

    if (OUT == 64) {
        float o0 = 0.f, o1 = 0.f;
#pragma unroll 8
        for (int k = 0; k < 64; k++) {
            float vk = sv[wid][k];
            o0 = fmaf(vk, sW[k * 64 + lane], o0);
            o1 = fmaf(vk, sW[k * 64 + lane + 32], o1);
        }
        o0 = (o0 > 0.f) ? o0 : 0.01f * o0;
        o1 = (o1 > 0.f) ? o1 : 0.01f * o1;
        hraw[(size_t)n * 64 + lane]      = o0;
        hraw[(size_t)n * 64 + 32 + lane] = o1;
        // repack to fp16 gather table via smem (dims 2*lane, 2*lane+1)
        __syncwarp();
        sv[wid][lane]      = o0;
        sv[wid][lane + 32] = o1;
        __syncwarp();
        *(__half2*)(hout16 + ((size_t)n << 6) + 2 * lane) =
            __floats2half2_rn(sv[wid][2 * lane], sv[wid][2 * lane + 1]);
        float ss = o0 * o0 + o1 * o1;
#pragma unroll
        for (int o = 16; o; o >>= 1) ss += __shfl_xor_sync(0xFFFFFFFF, ss, o);
        float sc = 1.f / fmaxf(sqrtf(ss), 1e-12f);
        out[(size_t)n * 160 + col0 + lane]      = o0 * sc;
        out[(size_t)n * 160 + col0 + 32 + lane] = o1 * sc;
    } else {
        float o0 = 0.f;
#pragma unroll 8
        for (int k = 0; k < 64; k++)
            o0 = fmaf(sv[wid][k], sW[k * 32 + lane], o0);
        o0 = (o0 > 0.f) ? o0 : 0.01f * o0;
        float ss = o0 * o0;
#pragma unroll
        for (int o = 16; o; o >>= 1) ss += __shfl_xor_sync(0xFFFFFFFF, ss, o);
        float sc = 1.f / fmaxf(sqrtf(ss), 1e-12f);
        out[(size_t)n * 160 + col0 + lane] = o0 * sc;
    }
}

// ================= launch =================================================
extern "C" void kernel_launch(void* const* d_in, const int* in_sizes, int n_in,
                              void* d_out, int out_size) {
    const float* ent = (const float*)d_in[0];   // [NE, 64]
    const float* rel = (const float*)d_in[1];   // [16, 64]
    const float* WR  = (const float*)d_in[2];   // [16, 64, 64]
    const float* W0  = (const float*)d_in[3];   // [64, 64]
    const float* W1  = (const float*)d_in[4];   // [64, 32]
    const void*  src = d_in[5];
    const void*  dst = d_in[6];
    const void*  et  = d_in[7];
    float* out = (float*)d_out;                 // [NE, 160]

    float* h1raw;   cudaGetSymbolAddress((void**)&h1raw, g_h1);
    __half* h1h;    cudaGetSymbolAddress((void**)&h1h,  g_h1h);
    __half* enth;   cudaGetSymbolAddress((void**)&enth, g_enth);

    k_init<<<SORT_B, 256>>>(ent, WR, src, et, out);      // 0
    k_roff1<<<NRL, 256>>>();                             // 1
    k_roff2<<<1, 32>>>();                                // 2
    k_proj<<<PROJ_GRID, 256>>>();                        // 3  <- ncu slot
    k_sort<<<SORT_B, 256>>>(src, dst, et);               // 4
    k_att<<<EE / 64, 256>>>(rel);                        // 5
    k_scan1<<<SCAN_B, 512>>>();                          // 6
    k_scan2<<<1, 32>>>();                                // 7
    k_scan3<<<SCAN_B, 512>>>();                          // 8
    k_scatter<<<EE / 256, 256>>>();                      // 9
    k_layer<64><<<NE / 8, 256>>>(ent,   enth, W0, h1raw, h1h, out, 64);
    k_layer<32><<<NE / 8, 256>>>(h1raw, h1h,  W1, h1raw, h1h, out, 128);
}